// round 1
// baseline (speedup 1.0000x reference)
#include <cuda_runtime.h>
#include <cuda_fp16.h>
#include <cstdint>

#define B_SZ 65536
#define H 256
#define BM 64
#define BNZ 128
#define BNS 64
#define BK 64
#define APAD 8
#define LDA (BK + APAD)   // 72 halves per smem row

// ---------------- scratch (static device arrays; no allocation) -------------
__device__ __half g_Wz[1024 * 512];   // [j*4+g][k]  k<256: W_ih, k>=256: W_hh
__device__ __half g_Ws[512 * 512];    // [j*2+g][k]  k<256: W_ih(tail), k>=256: W_sh
__device__ float  g_biasz[1024];
__device__ float  g_biass[512];

// ---------------- weight/bias reorder (runs every launch, ~1.5 MB) ---------
__global__ void reorder_kernel(const float* __restrict__ w_ih,
                               const float* __restrict__ w_hh,
                               const float* __restrict__ w_sh) {
    int tid = blockIdx.x * blockDim.x + threadIdx.x;   // 786432 threads total
    if (tid < 1024 * 512) {
        int r = tid >> 9, k = tid & 511;
        int j = r >> 2, g = r & 3;
        float v = (k < 256) ? w_ih[(g * 256 + j) * 256 + k]
                            : w_hh[(g * 256 + j) * 256 + (k - 256)];
        g_Wz[tid] = __float2half_rn(v);
    } else {
        int t2 = tid - 1024 * 512;
        int r = t2 >> 9, k = t2 & 511;
        int j = r >> 1, g = r & 1;
        float v = (k < 256) ? w_ih[((4 + g) * 256 + j) * 256 + k]
                            : w_sh[(g * 256 + j) * 256 + (k - 256)];
        g_Ws[t2] = __float2half_rn(v);
    }
}

__global__ void bias_kernel(const float* __restrict__ bi,
                            const float* __restrict__ bh,
                            const float* __restrict__ bs) {
    int t = blockIdx.x * blockDim.x + threadIdx.x;     // 1536 threads
    if (t < 1024) {
        int j = t >> 2, g = t & 3;
        g_biasz[t] = bi[g * 256 + j] + bh[g * 256 + j];
    } else if (t < 1536) {
        int t2 = t - 1024;
        int j = t2 >> 1, g = t2 & 1;
        g_biass[t2] = bi[(4 + g) * 256 + j] + bs[g * 256 + j];
    }
}

// ---------------- fused GEMM + LSTM epilogue --------------------------------
struct SmemTiles {
    __half A1[BM][LDA];    // input (phase1) / h (phase2)
    __half A2[BM][LDA];    // s (phase2 only)
    __half Wz[BNZ][LDA];
    __half Ws[BNS][LDA];
};
struct SmemEpi {
    float cz[BM][BNZ];
    float cs[BM][BNS];
};
union Smem { SmemTiles t; SmemEpi e; };

static __device__ __forceinline__ uint32_t smem_u32(const void* p) {
    return (uint32_t)__cvta_generic_to_shared(p);
}

static __device__ __forceinline__ void ldmatrix_x4(uint32_t* r, uint32_t addr) {
    asm volatile("ldmatrix.sync.aligned.m8n8.x4.shared.b16 {%0,%1,%2,%3}, [%4];"
                 : "=r"(r[0]), "=r"(r[1]), "=r"(r[2]), "=r"(r[3]) : "r"(addr));
}
static __device__ __forceinline__ void ldmatrix_x2(uint32_t& b0, uint32_t& b1, uint32_t addr) {
    asm volatile("ldmatrix.sync.aligned.m8n8.x2.shared.b16 {%0,%1}, [%2];"
                 : "=r"(b0), "=r"(b1) : "r"(addr));
}
static __device__ __forceinline__ void mma16816(float* c, const uint32_t* a,
                                                uint32_t b0, uint32_t b1) {
    asm volatile("mma.sync.aligned.m16n8k16.row.col.f32.f16.f16.f32 "
                 "{%0,%1,%2,%3}, {%4,%5,%6,%7}, {%8,%9}, {%0,%1,%2,%3};"
                 : "+f"(c[0]), "+f"(c[1]), "+f"(c[2]), "+f"(c[3])
                 : "r"(a[0]), "r"(a[1]), "r"(a[2]), "r"(a[3]), "r"(b0), "r"(b1));
}

__global__ void __launch_bounds__(256)
lstm_gemm_kernel(const float* __restrict__ x_in,
                 const float* __restrict__ h_in,
                 const float* __restrict__ c_in,
                 const float* __restrict__ s_all,
                 const float* __restrict__ mask,
                 const int*   __restrict__ idx_p,
                 float* __restrict__ out)
{
    __shared__ Smem smem;
    const int tid   = threadIdx.x;
    const int lane  = tid & 31;
    const int wid   = tid >> 5;
    const int warp_m = wid & 1;          // 2 warps along M
    const int warp_n = wid >> 1;         // 4 warps along N
    const int j0 = blockIdx.x * 32;      // 32 j's per CTA, 8 N-splits
    const int m0 = blockIdx.y * BM;
    const float* s_in = s_all + (long)(*idx_p) * ((long)B_SZ * H);

    float accz[8][4];                    // [mt*4 + nt][4]
    float accs[4][4];                    // [mt*2 + nt][4]
    #pragma unroll
    for (int i = 0; i < 8; i++)
        #pragma unroll
        for (int q = 0; q < 4; q++) accz[i][q] = 0.f;
    #pragma unroll
    for (int i = 0; i < 4; i++)
        #pragma unroll
        for (int q = 0; q < 4; q++) accs[i][q] = 0.f;

    // tile-load thread assignments
    const int ar  = tid >> 2;            // A: 64 rows, 4 col-groups of 16 floats
    const int ac  = (tid & 3) * 16;
    const int wzr = tid >> 1;            // Wz: 128 rows, 2 col-groups of 32 halves
    const int wzc = (tid & 1) * 32;
    const int wsr = tid >> 2;            // Ws: 64 rows, 4 col-groups of 16 halves
    const int wsc = (tid & 3) * 16;

    const __half* Wzg = g_Wz;
    const __half* Wsg = g_Ws;

    for (int kb = 0; kb < 512; kb += BK) {
        const bool ph1 = (kb < 256);
        const int  kg  = ph1 ? kb : (kb - 256);

        // A1 tile: input (phase1) or h (phase2)
        {
            const float* Az = ph1 ? x_in : h_in;
            const float4* src = (const float4*)(Az + (long)(m0 + ar) * 256 + kg + ac);
            #pragma unroll
            for (int i = 0; i < 4; i++) {
                float4 v = src[i];
                __half2 p0 = __floats2half2_rn(v.x, v.y);
                __half2 p1 = __floats2half2_rn(v.z, v.w);
                *(__half2*)&smem.t.A1[ar][ac + i * 4]     = p0;
                *(__half2*)&smem.t.A1[ar][ac + i * 4 + 2] = p1;
            }
        }
        // A2 tile: s (phase2 only)
        if (!ph1) {
            const float4* src = (const float4*)(s_in + (long)(m0 + ar) * 256 + kg + ac);
            #pragma unroll
            for (int i = 0; i < 4; i++) {
                float4 v = src[i];
                __half2 p0 = __floats2half2_rn(v.x, v.y);
                __half2 p1 = __floats2half2_rn(v.z, v.w);
                *(__half2*)&smem.t.A2[ar][ac + i * 4]     = p0;
                *(__half2*)&smem.t.A2[ar][ac + i * 4 + 2] = p1;
            }
        }
        // Wz tile: rows [j0*4, j0*4+128)
        {
            const uint4* src = (const uint4*)(Wzg + (long)(j0 * 4 + wzr) * 512 + kb + wzc);
            #pragma unroll
            for (int i = 0; i < 4; i++)
                *(uint4*)&smem.t.Wz[wzr][wzc + i * 8] = src[i];
        }
        // Ws tile: rows [j0*2, j0*2+64)
        {
            const uint4* src = (const uint4*)(Wsg + (long)(j0 * 2 + wsr) * 512 + kb + wsc);
            #pragma unroll
            for (int i = 0; i < 2; i++)
                *(uint4*)&smem.t.Ws[wsr][wsc + i * 8] = src[i];
        }
        __syncthreads();

        const __half (*As)[LDA] = ph1 ? smem.t.A1 : smem.t.A2;  // A for share gates

        #pragma unroll
        for (int kk = 0; kk < BK; kk += 16) {
            uint32_t a1[2][4], a2[2][4];
            #pragma unroll
            for (int mt = 0; mt < 2; mt++) {
                int row = warp_m * 32 + mt * 16 + (lane & 15);
                int col = kk + ((lane >> 4) << 3);
                ldmatrix_x4(a1[mt], smem_u32(&smem.t.A1[row][col]));
                ldmatrix_x4(a2[mt], smem_u32(&As[row][col]));
            }
            // z gates: Wz
            #pragma unroll
            for (int nt = 0; nt < 4; nt++) {
                int row = warp_n * 32 + nt * 8 + (lane & 7);
                int col = kk + ((lane >> 3) & 1) * 8;
                uint32_t b0, b1;
                ldmatrix_x2(b0, b1, smem_u32(&smem.t.Wz[row][col]));
                #pragma unroll
                for (int mt = 0; mt < 2; mt++)
                    mma16816(accz[mt * 4 + nt], a1[mt], b0, b1);
            }
            // share gates: Ws
            #pragma unroll
            for (int nt = 0; nt < 2; nt++) {
                int row = warp_n * 16 + nt * 8 + (lane & 7);
                int col = kk + ((lane >> 3) & 1) * 8;
                uint32_t b0, b1;
                ldmatrix_x2(b0, b1, smem_u32(&smem.t.Ws[row][col]));
                #pragma unroll
                for (int mt = 0; mt < 2; mt++)
                    mma16816(accs[mt * 2 + nt], a2[mt], b0, b1);
            }
        }
        __syncthreads();
    }

    // ---- exchange accumulators through smem so each thread owns full gates ----
    #pragma unroll
    for (int mt = 0; mt < 2; mt++) {
        int m = warp_m * 32 + mt * 16 + (lane >> 2);
        #pragma unroll
        for (int nt = 0; nt < 4; nt++) {
            float* c = accz[mt * 4 + nt];
            int n = warp_n * 32 + nt * 8 + (lane & 3) * 2;
            smem.e.cz[m][n]         = c[0];
            smem.e.cz[m][n + 1]     = c[1];
            smem.e.cz[m + 8][n]     = c[2];
            smem.e.cz[m + 8][n + 1] = c[3];
        }
        #pragma unroll
        for (int nt = 0; nt < 2; nt++) {
            float* c = accs[mt * 2 + nt];
            int n = warp_n * 16 + nt * 8 + (lane & 3) * 2;
            smem.e.cs[m][n]         = c[0];
            smem.e.cs[m][n + 1]     = c[1];
            smem.e.cs[m + 8][n]     = c[2];
            smem.e.cs[m + 8][n + 1] = c[3];
        }
    }
    __syncthreads();

    // ---- fused LSTM epilogue: 64 rows x 32 j's, 8 elems/thread ---------------
    #pragma unroll
    for (int it = 0; it < 8; it++) {
        int e  = tid + it * 256;
        int jl = e & 31;
        int ml = e >> 5;
        int row = m0 + ml;
        int jg  = j0 + jl;

        float z0 = smem.e.cz[ml][jl * 4 + 0] + g_biasz[jg * 4 + 0];
        float z1 = smem.e.cz[ml][jl * 4 + 1] + g_biasz[jg * 4 + 1];
        float z2 = smem.e.cz[ml][jl * 4 + 2] + g_biasz[jg * 4 + 2];
        float z3 = smem.e.cz[ml][jl * 4 + 3] + g_biasz[jg * 4 + 3];
        float sp0 = smem.e.cs[ml][jl * 2 + 0] + g_biass[jg * 2 + 0];
        float sp1 = smem.e.cs[ml][jl * 2 + 1] + g_biass[jg * 2 + 1];

        float mk   = mask[row];
        float cold = c_in[(long)row * H + jg];

        float gi = 1.f / (1.f + __expf(-z0));
        float gf = 1.f / (1.f + __expf(-z1));
        float go = 1.f / (1.f + __expf(-z2));
        float ch = tanhf(z3);
        float b0 = 1.f / (1.f + __expf(-sp0));
        float b1 = 1.f / (1.f + __expf(-sp1));

        float ct = (gf * cold + gi * ch) * mk;
        float tc = tanhf(ct) * mk;
        float hh = go * tc;

        long base = (long)row * H + jg;
        out[base]                     = hh;
        out[(long)B_SZ * H + base]    = ct;
        out[2L * B_SZ * H + base]     = b0 * tc;
        out[3L * B_SZ * H + base]     = b1 * tc;
    }
}

// ---------------- launch ----------------------------------------------------
extern "C" void kernel_launch(void* const* d_in, const int* in_sizes, int n_in,
                              void* d_out, int out_size) {
    const float* input = (const float*)d_in[0];
    const float* h_m   = (const float*)d_in[1];
    const float* c_m   = (const float*)d_in[2];
    const float* s_m   = (const float*)d_in[3];
    const float* mask  = (const float*)d_in[4];
    const float* w_ih  = (const float*)d_in[5];
    const float* w_hh  = (const float*)d_in[6];
    const float* w_sh  = (const float*)d_in[7];
    const float* b_ih  = (const float*)d_in[8];
    const float* b_hh  = (const float*)d_in[9];
    const float* b_sh  = (const float*)d_in[10];
    const int*   idx   = (const int*)d_in[11];
    float* out = (float*)d_out;

    reorder_kernel<<<768, 1024>>>(w_ih, w_hh, w_sh);
    bias_kernel<<<6, 256>>>(b_ih, b_hh, b_sh);

    dim3 grid(8, 1024);   // x = N-split (fast-varying -> L2 reuse of A), y = M-tile
    lstm_gemm_kernel<<<grid, 256>>>(input, h_m, c_m, s_m, mask, idx, out);
}

// round 4
// speedup vs baseline: 1.5438x; 1.5438x over previous
#include <cuda_runtime.h>
#include <cuda_fp16.h>
#include <cstdint>

#define B_SZ 65536
#define H 256

// ---------------- static scratch (no allocation) ----------------------------
__device__ __half g_Wz[1024 * 512];   // [j*4+g][k]  k<256: W_ih, else W_hh
__device__ __half g_Ws[512 * 512];    // [j*2+g][k]  k<256: W_ih(tail), else W_sh
__device__ __half g_Ax[(size_t)B_SZ * 256];
__device__ __half g_Ah[(size_t)B_SZ * 256];
__device__ __half g_As[(size_t)B_SZ * 256];
__device__ float  g_biasz[1024];
__device__ float  g_biass[512];

// ---------------- prepass kernels -------------------------------------------
__global__ void reorder_kernel(const float* __restrict__ w_ih,
                               const float* __restrict__ w_hh,
                               const float* __restrict__ w_sh) {
    int tid = blockIdx.x * blockDim.x + threadIdx.x;
    if (tid < 1024 * 512) {
        int r = tid >> 9, k = tid & 511;
        int j = r >> 2, g = r & 3;
        float v = (k < 256) ? w_ih[(g * 256 + j) * 256 + k]
                            : w_hh[(g * 256 + j) * 256 + (k - 256)];
        g_Wz[tid] = __float2half_rn(v);
    } else {
        int t2 = tid - 1024 * 512;
        int r = t2 >> 9, k = t2 & 511;
        int j = r >> 1, g = r & 1;
        float v = (k < 256) ? w_ih[((4 + g) * 256 + j) * 256 + k]
                            : w_sh[(g * 256 + j) * 256 + (k - 256)];
        g_Ws[t2] = __float2half_rn(v);
    }
}

__global__ void bias_kernel(const float* __restrict__ bi,
                            const float* __restrict__ bh,
                            const float* __restrict__ bs) {
    int t = blockIdx.x * blockDim.x + threadIdx.x;
    if (t < 1024) {
        int j = t >> 2, g = t & 3;
        g_biasz[t] = bi[g * 256 + j] + bh[g * 256 + j];
    } else if (t < 1536) {
        int t2 = t - 1024;
        int j = t2 >> 1, g = t2 & 1;
        g_biass[t2] = bi[(4 + g) * 256 + j] + bs[g * 256 + j];
    }
}

static __device__ __forceinline__ uint32_t h2u(__half2 h) {
    union { __half2 h; uint32_t u; } c; c.h = h; return c.u;
}

__global__ void aconv_kernel(const float* __restrict__ x,
                             const float* __restrict__ hm,
                             const float* __restrict__ s_all,
                             const int* __restrict__ idxp) {
    size_t gid = (size_t)blockIdx.x * blockDim.x + threadIdx.x;
    size_t off = gid * 4;
    const float* src; __half* dst;
    if (blockIdx.y == 0)      { src = x;  dst = g_Ax; }
    else if (blockIdx.y == 1) { src = hm; dst = g_Ah; }
    else { src = s_all + (size_t)(*idxp) * ((size_t)B_SZ * 256); dst = g_As; }
    float4 v = *(const float4*)(src + off);
    uint2 p;
    p.x = h2u(__floats2half2_rn(v.x, v.y));
    p.y = h2u(__floats2half2_rn(v.z, v.w));
    *(uint2*)(dst + off) = p;
}

// ---------------- PTX helpers ------------------------------------------------
static __device__ __forceinline__ uint32_t smem_u32(const void* p) {
    return (uint32_t)__cvta_generic_to_shared(p);
}
static __device__ __forceinline__ void cp16(uint32_t dst, const void* src) {
    asm volatile("cp.async.cg.shared.global [%0], [%1], 16;"
                 :: "r"(dst), "l"(src) : "memory");
}
static __device__ __forceinline__ void cp_commit() {
    asm volatile("cp.async.commit_group;" ::: "memory");
}
static __device__ __forceinline__ void ldmatrix_x4(uint32_t* r, uint32_t addr) {
    asm volatile("ldmatrix.sync.aligned.m8n8.x4.shared.b16 {%0,%1,%2,%3}, [%4];"
                 : "=r"(r[0]), "=r"(r[1]), "=r"(r[2]), "=r"(r[3]) : "r"(addr));
}
static __device__ __forceinline__ void ldmatrix_x2(uint32_t& b0, uint32_t& b1, uint32_t addr) {
    asm volatile("ldmatrix.sync.aligned.m8n8.x2.shared.b16 {%0,%1}, [%2];"
                 : "=r"(b0), "=r"(b1) : "r"(addr));
}
static __device__ __forceinline__ void mma16816(float* c, const uint32_t* a,
                                                uint32_t b0, uint32_t b1) {
    asm volatile("mma.sync.aligned.m16n8k16.row.col.f32.f16.f16.f32 "
                 "{%0,%1,%2,%3}, {%4,%5,%6,%7}, {%8,%9}, {%0,%1,%2,%3};"
                 : "+f"(c[0]), "+f"(c[1]), "+f"(c[2]), "+f"(c[3])
                 : "r"(a[0]), "r"(a[1]), "r"(a[2]), "r"(a[3]), "r"(b0), "r"(b1));
}
static __device__ __forceinline__ uint32_t swz(uint32_t o) {
    return o ^ ((o >> 3) & 0x70);
}

// SMEM layout (bytes):
//   [0,1024)      biasz (256 f32)
//   [1024,1536)   biass (128 f32)
//   [2048, +80K)  stage0:  A1 16K | A2 16K | Wz 32K | Ws 16K
//   [83968,+80K)  stage1
//   epilogue reuses [2048,...): scz 64x256 f32 (64K), scs 64x128 f32 (32K)
#define SM_STG(s)  (2048 + (s) * 81920)
#define OFF_A2 16384
#define OFF_WZ 32768
#define OFF_WS 65536
#define SMEM_TOTAL (2048 + 2 * 81920)

// ---------------- fused HMMA GEMM + LSTM epilogue ---------------------------
__global__ void __launch_bounds__(512, 1)
lstm_hmma_kernel(const float* __restrict__ c_in,
                 const float* __restrict__ mask,
                 float* __restrict__ out)
{
    extern __shared__ char smem[];
    const int tid  = threadIdx.x;
    const int lane = tid & 31;
    const int wid  = tid >> 5;
    const int warp_m = wid & 3;           // 4 warps along M (32 rows each)
    const int warp_n = wid >> 2;          // 4 warps along N (z64 + s32 cols each)
    const int j0 = blockIdx.x * 64;       // 4 j-splits
    const int m0 = blockIdx.y * 128;      // 512 M-tiles

    // stage biases
    if (tid < 256)      ((float*)smem)[tid] = g_biasz[j0 * 4 + tid];
    else if (tid < 384) ((float*)(smem + 1024))[tid - 256] = g_biass[j0 * 2 + (tid - 256)];

    float accz[2][8][4], accs[2][4][4];
    #pragma unroll
    for (int mt = 0; mt < 2; mt++) {
        #pragma unroll
        for (int f = 0; f < 8; f++)
            #pragma unroll
            for (int q = 0; q < 4; q++) accz[mt][f][q] = 0.f;
        #pragma unroll
        for (int f = 0; f < 4; f++)
            #pragma unroll
            for (int q = 0; q < 4; q++) accs[mt][f][q] = 0.f;
    }

    auto issue_stage = [&](int kb) {
        const int st = kb & 1;
        const uint32_t sg = smem_u32(smem) + SM_STG(st);
        const bool ph1 = (kb < 4);
        const int c0 = (ph1 ? kb : kb - 4) * 64;
        const __half* a1g = ph1 ? g_Ax : g_Ah;
        #pragma unroll
        for (int i = 0; i < 2; i++) {        // A1: 128 rows x 128B
            int id = tid + i * 512, r = id >> 3, cc = id & 7;
            cp16(sg + swz(r * 128 + cc * 16),
                 a1g + (size_t)(m0 + r) * 256 + c0 + cc * 8);
        }
        if (!ph1) {
            #pragma unroll
            for (int i = 0; i < 2; i++) {    // A2 = s tile
                int id = tid + i * 512, r = id >> 3, cc = id & 7;
                cp16(sg + OFF_A2 + swz(r * 128 + cc * 16),
                     g_As + (size_t)(m0 + r) * 256 + c0 + cc * 8);
            }
        }
        #pragma unroll
        for (int i = 0; i < 4; i++) {        // Wz: 256 rows x 128B
            int id = tid + i * 512, r = id >> 3, cc = id & 7;
            cp16(sg + OFF_WZ + swz(r * 128 + cc * 16),
                 g_Wz + (size_t)(j0 * 4 + r) * 512 + kb * 64 + cc * 8);
        }
        #pragma unroll
        for (int i = 0; i < 2; i++) {        // Ws: 128 rows x 128B
            int id = tid + i * 512, r = id >> 3, cc = id & 7;
            cp16(sg + OFF_WS + swz(r * 128 + cc * 16),
                 g_Ws + (size_t)(j0 * 2 + r) * 512 + kb * 64 + cc * 8);
        }
        cp_commit();
    };

    issue_stage(0);

    for (int kb = 0; kb < 8; kb++) {
        if (kb < 7) {
            issue_stage(kb + 1);
            asm volatile("cp.async.wait_group 1;" ::: "memory");
        } else {
            asm volatile("cp.async.wait_group 0;" ::: "memory");
        }
        __syncthreads();

        const uint32_t sg  = smem_u32(smem) + SM_STG(kb & 1);
        const bool ph1 = (kb < 4);
        const uint32_t A1b = sg;
        const uint32_t Asb = ph1 ? sg : (sg + OFF_A2);
        const uint32_t Wzb = sg + OFF_WZ;
        const uint32_t Wsb = sg + OFF_WS;

        #pragma unroll
        for (int kk = 0; kk < 64; kk += 16) {
            uint32_t az[2][4], as_[2][4];
            #pragma unroll
            for (int mt = 0; mt < 2; mt++) {
                int row = warp_m * 32 + mt * 16 + (lane & 15);
                uint32_t off = swz(row * 128 + kk * 2 + (lane >> 4) * 16);
                ldmatrix_x4(az[mt],  A1b + off);
                ldmatrix_x4(as_[mt], Asb + off);
            }
            // share gates first (frees as_)
            #pragma unroll
            for (int f = 0; f < 4; f++) {
                int row = warp_n * 32 + f * 8 + (lane & 7);
                uint32_t b0, b1;
                ldmatrix_x2(b0, b1, Wsb + swz(row * 128 + kk * 2 + ((lane >> 3) & 1) * 16));
                mma16816(accs[0][f], as_[0], b0, b1);
                mma16816(accs[1][f], as_[1], b0, b1);
            }
            // z gates
            #pragma unroll
            for (int f = 0; f < 8; f++) {
                int row = warp_n * 64 + f * 8 + (lane & 7);
                uint32_t b0, b1;
                ldmatrix_x2(b0, b1, Wzb + swz(row * 128 + kk * 2 + ((lane >> 3) & 1) * 16));
                mma16816(accz[0][f], az[0], b0, b1);
                mma16816(accz[1][f], az[1], b0, b1);
            }
        }
        __syncthreads();
    }

    // ---- epilogue: 2 half-row passes through smem ---------------------------
    const float* sBz = (const float*)smem;
    const float* sBs = (const float*)(smem + 1024);
    float* scz = (float*)(smem + 2048);            // [64][256]
    float* scs = (float*)(smem + 2048 + 65536);    // [64][128]

    #pragma unroll
    for (int p = 0; p < 2; p++) {
        if ((warp_m >> 1) == p) {
            #pragma unroll
            for (int mt = 0; mt < 2; mt++) {
                int r0 = (warp_m & 1) * 32 + mt * 16 + (lane >> 2);
                #pragma unroll
                for (int f = 0; f < 8; f++) {
                    int cb = warp_n * 64 + f * 8 + (lane & 3) * 2;
                    scz[r0 * 256 + cb]           = accz[mt][f][0];
                    scz[r0 * 256 + cb + 1]       = accz[mt][f][1];
                    scz[(r0 + 8) * 256 + cb]     = accz[mt][f][2];
                    scz[(r0 + 8) * 256 + cb + 1] = accz[mt][f][3];
                }
                #pragma unroll
                for (int f = 0; f < 4; f++) {
                    int cb = warp_n * 32 + f * 8 + (lane & 3) * 2;
                    scs[r0 * 128 + cb]           = accs[mt][f][0];
                    scs[r0 * 128 + cb + 1]       = accs[mt][f][1];
                    scs[(r0 + 8) * 128 + cb]     = accs[mt][f][2];
                    scs[(r0 + 8) * 128 + cb + 1] = accs[mt][f][3];
                }
            }
        }
        __syncthreads();

        #pragma unroll
        for (int it = 0; it < 8; it++) {
            int e  = tid + it * 512;
            int jl = e & 63, ml = e >> 6;
            int row = m0 + p * 64 + ml;
            int jg  = j0 + jl;

            float z0 = scz[ml * 256 + jl * 4 + 0] + sBz[jl * 4 + 0];
            float z1 = scz[ml * 256 + jl * 4 + 1] + sBz[jl * 4 + 1];
            float z2 = scz[ml * 256 + jl * 4 + 2] + sBz[jl * 4 + 2];
            float z3 = scz[ml * 256 + jl * 4 + 3] + sBz[jl * 4 + 3];
            float p0 = scs[ml * 128 + jl * 2 + 0] + sBs[jl * 2 + 0];
            float p1 = scs[ml * 128 + jl * 2 + 1] + sBs[jl * 2 + 1];

            float mk   = mask[row];
            float cold = c_in[(size_t)row * H + jg];

            float gi = 1.f / (1.f + __expf(-z0));
            float gf = 1.f / (1.f + __expf(-z1));
            float go = 1.f / (1.f + __expf(-z2));
            float ch = tanhf(z3);
            float b0 = 1.f / (1.f + __expf(-p0));
            float b1 = 1.f / (1.f + __expf(-p1));

            float ct = (gf * cold + gi * ch) * mk;
            float tc = tanhf(ct) * mk;

            size_t base = (size_t)row * H + jg;
            out[base]                      = go * tc;
            out[(size_t)B_SZ * H + base]   = ct;
            out[2ull * B_SZ * H + base]    = b0 * tc;
            out[3ull * B_SZ * H + base]    = b1 * tc;
        }
        __syncthreads();
    }
}

// ---------------- launch -----------------------------------------------------
extern "C" void kernel_launch(void* const* d_in, const int* in_sizes, int n_in,
                              void* d_out, int out_size) {
    const float* input = (const float*)d_in[0];
    const float* h_m   = (const float*)d_in[1];
    const float* c_m   = (const float*)d_in[2];
    const float* s_m   = (const float*)d_in[3];
    const float* mask  = (const float*)d_in[4];
    const float* w_ih  = (const float*)d_in[5];
    const float* w_hh  = (const float*)d_in[6];
    const float* w_sh  = (const float*)d_in[7];
    const float* b_ih  = (const float*)d_in[8];
    const float* b_hh  = (const float*)d_in[9];
    const float* b_sh  = (const float*)d_in[10];
    const int*   idx   = (const int*)d_in[11];
    float* out = (float*)d_out;

    reorder_kernel<<<768, 1024>>>(w_ih, w_hh, w_sh);
    bias_kernel<<<6, 256>>>(b_ih, b_hh, b_sh);
    aconv_kernel<<<dim3(B_SZ * 256 / 4 / 256, 3), 256>>>(input, h_m, s_m, idx);

    static int smem_set = 0;
    if (!smem_set) {
        cudaFuncSetAttribute(lstm_hmma_kernel,
                             cudaFuncAttributeMaxDynamicSharedMemorySize, SMEM_TOTAL);
        smem_set = 1;
    }
    dim3 grid(4, 512);   // x = j-split (fast -> A L2 reuse), y = M-tile
    lstm_hmma_kernel<<<grid, 512, SMEM_TOTAL>>>(c_m, mask, out);
}

// round 5
// speedup vs baseline: 1.6881x; 1.0935x over previous
#include <cuda_runtime.h>
#include <cuda_fp16.h>
#include <cstdint>

#define B_SZ 65536
#define H 256

// ---------------- static scratch (no allocation) ----------------------------
// Wz layout: row r = jhi*64 + g*16 + jlo  (j = jhi*16+jlo, g in 0..3), 512 k
// Ws layout: row r = jhi*32 + g*16 + jlo  (g in 0..1), 512 k
__device__ __half g_Wz[1024 * 512];
__device__ __half g_Ws[512 * 512];
__device__ __half g_Ax[(size_t)B_SZ * 256];
__device__ __half g_Ah[(size_t)B_SZ * 256];
__device__ __half g_As[(size_t)B_SZ * 256];
__device__ float  g_biasz[1024];   // [g*256 + j]
__device__ float  g_biass[512];    // [g*256 + j]

// ---------------- prepass kernels -------------------------------------------
__global__ void reorder_kernel(const float* __restrict__ w_ih,
                               const float* __restrict__ w_hh,
                               const float* __restrict__ w_sh) {
    int tid = blockIdx.x * blockDim.x + threadIdx.x;
    if (tid < 1024 * 512) {
        int r = tid >> 9, k = tid & 511;
        int jhi = r >> 6, g = (r >> 4) & 3, jlo = r & 15;
        int j = jhi * 16 + jlo;
        float v = (k < 256) ? w_ih[(g * 256 + j) * 256 + k]
                            : w_hh[(g * 256 + j) * 256 + (k - 256)];
        g_Wz[tid] = __float2half_rn(v);
    } else {
        int t2 = tid - 1024 * 512;
        int r = t2 >> 9, k = t2 & 511;
        int jhi = r >> 5, g = (r >> 4) & 1, jlo = r & 15;
        int j = jhi * 16 + jlo;
        float v = (k < 256) ? w_ih[((4 + g) * 256 + j) * 256 + k]
                            : w_sh[(g * 256 + j) * 256 + (k - 256)];
        g_Ws[t2] = __float2half_rn(v);
    }
}

__global__ void bias_kernel(const float* __restrict__ bi,
                            const float* __restrict__ bh,
                            const float* __restrict__ bs) {
    int t = blockIdx.x * blockDim.x + threadIdx.x;
    if (t < 1024)      g_biasz[t] = bi[t] + bh[t];
    else if (t < 1536) g_biass[t - 1024] = bi[1024 + (t - 1024)] + bs[t - 1024];
}

static __device__ __forceinline__ uint32_t h2u(__half2 h) {
    union { __half2 h; uint32_t u; } c; c.h = h; return c.u;
}

__global__ void aconv_kernel(const float* __restrict__ x,
                             const float* __restrict__ hm,
                             const float* __restrict__ s_all,
                             const int* __restrict__ idxp) {
    size_t gid = (size_t)blockIdx.x * blockDim.x + threadIdx.x;
    size_t off = gid * 4;
    const float* src; __half* dst;
    if (blockIdx.y == 0)      { src = x;  dst = g_Ax; }
    else if (blockIdx.y == 1) { src = hm; dst = g_Ah; }
    else { src = s_all + (size_t)(*idxp) * ((size_t)B_SZ * 256); dst = g_As; }
    float4 v = *(const float4*)(src + off);
    uint2 p;
    p.x = h2u(__floats2half2_rn(v.x, v.y));
    p.y = h2u(__floats2half2_rn(v.z, v.w));
    *(uint2*)(dst + off) = p;
}

// ---------------- PTX helpers ------------------------------------------------
static __device__ __forceinline__ uint32_t smem_u32(const void* p) {
    return (uint32_t)__cvta_generic_to_shared(p);
}
static __device__ __forceinline__ void cp16(uint32_t dst, const void* src) {
    asm volatile("cp.async.cg.shared.global [%0], [%1], 16;"
                 :: "r"(dst), "l"(src) : "memory");
}
static __device__ __forceinline__ void cp_commit() {
    asm volatile("cp.async.commit_group;" ::: "memory");
}
static __device__ __forceinline__ void ldmatrix_x4(uint32_t* r, uint32_t addr) {
    asm volatile("ldmatrix.sync.aligned.m8n8.x4.shared.b16 {%0,%1,%2,%3}, [%4];"
                 : "=r"(r[0]), "=r"(r[1]), "=r"(r[2]), "=r"(r[3]) : "r"(addr));
}
static __device__ __forceinline__ void mma16816(float* c, const uint32_t* a,
                                                uint32_t b0, uint32_t b1) {
    asm volatile("mma.sync.aligned.m16n8k16.row.col.f32.f16.f16.f32 "
                 "{%0,%1,%2,%3}, {%4,%5,%6,%7}, {%8,%9}, {%0,%1,%2,%3};"
                 : "+f"(c[0]), "+f"(c[1]), "+f"(c[2]), "+f"(c[3])
                 : "r"(a[0]), "r"(a[1]), "r"(a[2]), "r"(a[3]), "r"(b0), "r"(b1));
}
static __device__ __forceinline__ uint32_t swz(uint32_t o) {
    return o ^ ((o >> 3) & 0x70);
}

// SMEM: [0,1024) sBz [g*64+jl], [1024,1536) sBs, stages at 2048
#define SM_STG(s)  (2048 + (s) * 81920)
#define OFF_A2 16384
#define OFF_WZ 32768
#define OFF_WS 65536
#define SMEM_TOTAL (2048 + 2 * 81920)

// ---------------- fused HMMA GEMM + LSTM epilogue ---------------------------
__global__ void __launch_bounds__(512, 1)
lstm_hmma_kernel(const float* __restrict__ c_in,
                 const float* __restrict__ mask,
                 float* __restrict__ out)
{
    extern __shared__ char smem[];
    const int tid  = threadIdx.x;
    const int lane = tid & 31;
    const int wid  = tid >> 5;
    const int warp_m = wid & 3;           // 4 warps x 32 rows
    const int warp_n = wid >> 2;          // 4 warps x (16 j = z64 + s32 cols)
    const int j0 = blockIdx.x * 64;
    const int m0 = blockIdx.y * 128;

    // stage biases into smem in [g][jl] form
    if (tid < 256)      ((float*)smem)[tid] = g_biasz[(tid >> 6) * 256 + j0 + (tid & 63)];
    else if (tid < 384) {
        int tt = tid - 256;
        ((float*)(smem + 1024))[tt] = g_biass[(tt >> 6) * 256 + j0 + (tt & 63)];
    }

    float accz[2][8][4], accs[2][4][4];
    #pragma unroll
    for (int mt = 0; mt < 2; mt++) {
        #pragma unroll
        for (int f = 0; f < 8; f++)
            #pragma unroll
            for (int q = 0; q < 4; q++) accz[mt][f][q] = 0.f;
        #pragma unroll
        for (int f = 0; f < 4; f++)
            #pragma unroll
            for (int q = 0; q < 4; q++) accs[mt][f][q] = 0.f;
    }

    // fragment addressing (stage-relative offsets + xor masks)
    const uint32_t rowA  = warp_m * 32 + (lane & 15);       // + mt*16
    const uint32_t axA   = (((lane & 7) * 16)) ^ ((lane >> 4) * 16);
    const uint32_t offA  = rowA * 128;
    const uint32_t rowB0 = ((lane >> 4) & 1) * 8 + (lane & 7);  // + fp*16 + warp_n*tile
    const uint32_t axB   = ((lane & 7) * 16) ^ (((lane >> 3) & 1) * 16);
    const uint32_t offBz = (warp_n * 64 + rowB0) * 128;
    const uint32_t offBs = (warp_n * 32 + rowB0) * 128;
    const uint32_t sbase = smem_u32(smem);

    auto issue_stage = [&](int kb) {
        const uint32_t sg = sbase + SM_STG(kb & 1);
        const bool ph1 = (kb < 4);
        const int c0 = (ph1 ? kb : kb - 4) * 64;
        const __half* a1g = ph1 ? g_Ax : g_Ah;
        #pragma unroll
        for (int i = 0; i < 2; i++) {
            int id = tid + i * 512, r = id >> 3, cc = id & 7;
            cp16(sg + swz(r * 128 + cc * 16),
                 a1g + (size_t)(m0 + r) * 256 + c0 + cc * 8);
        }
        if (!ph1) {
            #pragma unroll
            for (int i = 0; i < 2; i++) {
                int id = tid + i * 512, r = id >> 3, cc = id & 7;
                cp16(sg + OFF_A2 + swz(r * 128 + cc * 16),
                     g_As + (size_t)(m0 + r) * 256 + c0 + cc * 8);
            }
        }
        #pragma unroll
        for (int i = 0; i < 4; i++) {
            int id = tid + i * 512, r = id >> 3, cc = id & 7;
            cp16(sg + OFF_WZ + swz(r * 128 + cc * 16),
                 g_Wz + (size_t)(j0 * 4 + r) * 512 + kb * 64 + cc * 8);
        }
        #pragma unroll
        for (int i = 0; i < 2; i++) {
            int id = tid + i * 512, r = id >> 3, cc = id & 7;
            cp16(sg + OFF_WS + swz(r * 128 + cc * 16),
                 g_Ws + (size_t)(j0 * 2 + r) * 512 + kb * 64 + cc * 8);
        }
        cp_commit();
    };

    issue_stage(0);

    #pragma unroll 1
    for (int kb = 0; kb < 8; kb++) {
        if (kb < 7) {
            issue_stage(kb + 1);
            asm volatile("cp.async.wait_group 1;" ::: "memory");
        } else {
            asm volatile("cp.async.wait_group 0;" ::: "memory");
        }
        __syncthreads();

        const uint32_t sg = sbase + SM_STG(kb & 1);
        const bool ph2 = (kb >= 4);
        const uint32_t A1b = sg + offA;
        const uint32_t A2b = sg + OFF_A2 + offA;
        const uint32_t Wzb = sg + OFF_WZ + offBz;
        const uint32_t Wsb = sg + OFF_WS + offBs;

        #pragma unroll
        for (int kk4 = 0; kk4 < 4; kk4++) {
            const uint32_t KK2 = kk4 * 32;
            uint32_t az[2][4];
            ldmatrix_x4(az[0], A1b + (KK2 ^ axA));
            ldmatrix_x4(az[1], A1b + 16 * 128 + (KK2 ^ axA));
            uint32_t as_[2][4];
            if (ph2) {
                ldmatrix_x4(as_[0], A2b + (KK2 ^ axA));
                ldmatrix_x4(as_[1], A2b + 16 * 128 + (KK2 ^ axA));
            } else {
                #pragma unroll
                for (int q = 0; q < 4; q++) { as_[0][q] = az[0][q]; as_[1][q] = az[1][q]; }
            }
            // share gates (B fragments via x4: (f,f+1) x (k0,k8))
            #pragma unroll
            for (int fp = 0; fp < 2; fp++) {
                uint32_t b[4];
                ldmatrix_x4(b, Wsb + fp * (16 * 128) + (KK2 ^ axB));
                mma16816(accs[0][2 * fp],     as_[0], b[0], b[1]);
                mma16816(accs[1][2 * fp],     as_[1], b[0], b[1]);
                mma16816(accs[0][2 * fp + 1], as_[0], b[2], b[3]);
                mma16816(accs[1][2 * fp + 1], as_[1], b[2], b[3]);
            }
            // z gates
            #pragma unroll
            for (int fp = 0; fp < 4; fp++) {
                uint32_t b[4];
                ldmatrix_x4(b, Wzb + fp * (16 * 128) + (KK2 ^ axB));
                mma16816(accz[0][2 * fp],     az[0], b[0], b[1]);
                mma16816(accz[1][2 * fp],     az[1], b[0], b[1]);
                mma16816(accz[0][2 * fp + 1], az[0], b[2], b[3]);
                mma16816(accz[1][2 * fp + 1], az[1], b[2], b[3]);
            }
        }
        __syncthreads();
    }

    // ---- register-resident epilogue ----------------------------------------
    // col = g*16 + jh*8 + (lane&3)*2 + dj  ->  f = g*2 + jh
    const float* sBz = (const float*)smem;
    const float* sBs = (const float*)(smem + 1024);
    const int jb = warp_n * 16 + (lane & 3) * 2;   // CTA-local j base (+ jh*8 + dj)

    #pragma unroll
    for (int mt = 0; mt < 2; mt++) {
        #pragma unroll
        for (int rh = 0; rh < 2; rh++) {
            const int row = m0 + warp_m * 32 + mt * 16 + rh * 8 + (lane >> 2);
            const float mk = mask[row];
            const float* crow = c_in + (size_t)row * H;
            float* orow = out + (size_t)row * H;
            #pragma unroll
            for (int jh = 0; jh < 2; jh++) {
                const int jl = jb + jh * 8;
                const int jg = j0 + jl;
                const float2 cold = *(const float2*)(crow + jg);
                float2 hv, cv, s0v, s1v;
                #pragma unroll
                for (int dj = 0; dj < 2; dj++) {
                    const int q = rh * 2 + dj;
                    float z0 = accz[mt][0 + jh][q] + sBz[0 * 64 + jl + dj];
                    float z1 = accz[mt][2 + jh][q] + sBz[1 * 64 + jl + dj];
                    float z2 = accz[mt][4 + jh][q] + sBz[2 * 64 + jl + dj];
                    float z3 = accz[mt][6 + jh][q] + sBz[3 * 64 + jl + dj];
                    float p0 = accs[mt][0 + jh][q] + sBs[0 * 64 + jl + dj];
                    float p1 = accs[mt][2 + jh][q] + sBs[1 * 64 + jl + dj];

                    float gi = 1.f / (1.f + __expf(-z0));
                    float gf = 1.f / (1.f + __expf(-z1));
                    float go = 1.f / (1.f + __expf(-z2));
                    float ch = tanhf(z3);
                    float b0 = 1.f / (1.f + __expf(-p0));
                    float b1 = 1.f / (1.f + __expf(-p1));

                    float cc = (dj == 0) ? cold.x : cold.y;
                    float ct = (gf * cc + gi * ch) * mk;
                    float tc = tanhf(ct) * mk;
                    (&hv.x)[dj]  = go * tc;
                    (&cv.x)[dj]  = ct;
                    (&s0v.x)[dj] = b0 * tc;
                    (&s1v.x)[dj] = b1 * tc;
                }
                *(float2*)(orow + jg)                      = hv;
                *(float2*)(orow + (size_t)B_SZ * H + jg)   = cv;
                *(float2*)(orow + 2ull * B_SZ * H + jg)    = s0v;
                *(float2*)(orow + 3ull * B_SZ * H + jg)    = s1v;
            }
        }
    }
}

// ---------------- launch -----------------------------------------------------
extern "C" void kernel_launch(void* const* d_in, const int* in_sizes, int n_in,
                              void* d_out, int out_size) {
    const float* input = (const float*)d_in[0];
    const float* h_m   = (const float*)d_in[1];
    const float* c_m   = (const float*)d_in[2];
    const float* s_m   = (const float*)d_in[3];
    const float* mask  = (const float*)d_in[4];
    const float* w_ih  = (const float*)d_in[5];
    const float* w_hh  = (const float*)d_in[6];
    const float* w_sh  = (const float*)d_in[7];
    const float* b_ih  = (const float*)d_in[8];
    const float* b_hh  = (const float*)d_in[9];
    const float* b_sh  = (const float*)d_in[10];
    const int*   idx   = (const int*)d_in[11];
    float* out = (float*)d_out;

    reorder_kernel<<<768, 1024>>>(w_ih, w_hh, w_sh);
    bias_kernel<<<6, 256>>>(b_ih, b_hh, b_sh);
    aconv_kernel<<<dim3(B_SZ * 256 / 4 / 256, 3), 256>>>(input, h_m, s_m, idx);

    static int smem_set = 0;
    if (!smem_set) {
        cudaFuncSetAttribute(lstm_hmma_kernel,
                             cudaFuncAttributeMaxDynamicSharedMemorySize, SMEM_TOTAL);
        smem_set = 1;
    }
    dim3 grid(4, 512);
    lstm_hmma_kernel<<<grid, 512, SMEM_TOTAL>>>(c_m, mask, out);
}

// round 6
// speedup vs baseline: 1.9816x; 1.1739x over previous
#include <cuda_runtime.h>
#include <cuda_fp16.h>
#include <cstdint>

#define B_SZ 65536
#define H 256

// ---------------- static scratch (no allocation) ----------------------------
// Wz layout: row r = jhi*64 + g*16 + jlo  (j = jhi*16+jlo, g in 0..3), 512 k
// Ws layout: row r = jhi*32 + g*16 + jlo  (g in 0..1), 512 k
__device__ __half g_Wz[1024 * 512];
__device__ __half g_Ws[512 * 512];
__device__ __half g_Ax[(size_t)B_SZ * 256];
__device__ __half g_Ah[(size_t)B_SZ * 256];
__device__ __half g_As[(size_t)B_SZ * 256];
__device__ float  g_biasz[1024];   // [g*256 + j]
__device__ float  g_biass[512];    // [g*256 + j]

// ---------------- prepass kernels -------------------------------------------
__global__ void reorder_kernel(const float* __restrict__ w_ih,
                               const float* __restrict__ w_hh,
                               const float* __restrict__ w_sh) {
    int tid = blockIdx.x * blockDim.x + threadIdx.x;
    if (tid < 1024 * 512) {
        int r = tid >> 9, k = tid & 511;
        int jhi = r >> 6, g = (r >> 4) & 3, jlo = r & 15;
        int j = jhi * 16 + jlo;
        float v = (k < 256) ? w_ih[(g * 256 + j) * 256 + k]
                            : w_hh[(g * 256 + j) * 256 + (k - 256)];
        g_Wz[tid] = __float2half_rn(v);
    } else {
        int t2 = tid - 1024 * 512;
        int r = t2 >> 9, k = t2 & 511;
        int jhi = r >> 5, g = (r >> 4) & 1, jlo = r & 15;
        int j = jhi * 16 + jlo;
        float v = (k < 256) ? w_ih[((4 + g) * 256 + j) * 256 + k]
                            : w_sh[(g * 256 + j) * 256 + (k - 256)];
        g_Ws[t2] = __float2half_rn(v);
    }
}

__global__ void bias_kernel(const float* __restrict__ bi,
                            const float* __restrict__ bh,
                            const float* __restrict__ bs) {
    int t = blockIdx.x * blockDim.x + threadIdx.x;
    if (t < 1024)      g_biasz[t] = bi[t] + bh[t];
    else if (t < 1536) g_biass[t - 1024] = bi[1024 + (t - 1024)] + bs[t - 1024];
}

static __device__ __forceinline__ uint32_t h2u(__half2 h) {
    union { __half2 h; uint32_t u; } c; c.h = h; return c.u;
}

__global__ void aconv_kernel(const float* __restrict__ x,
                             const float* __restrict__ hm,
                             const float* __restrict__ s_all,
                             const int* __restrict__ idxp) {
    size_t gid = (size_t)blockIdx.x * blockDim.x + threadIdx.x;
    size_t off = gid * 4;
    const float* src; __half* dst;
    if (blockIdx.y == 0)      { src = x;  dst = g_Ax; }
    else if (blockIdx.y == 1) { src = hm; dst = g_Ah; }
    else { src = s_all + (size_t)(*idxp) * ((size_t)B_SZ * 256); dst = g_As; }
    float4 v = *(const float4*)(src + off);
    uint2 p;
    p.x = h2u(__floats2half2_rn(v.x, v.y));
    p.y = h2u(__floats2half2_rn(v.z, v.w));
    *(uint2*)(dst + off) = p;
}

// ---------------- PTX helpers ------------------------------------------------
static __device__ __forceinline__ uint32_t smem_u32(const void* p) {
    return (uint32_t)__cvta_generic_to_shared(p);
}
static __device__ __forceinline__ void cp16(uint32_t dst, const void* src) {
    asm volatile("cp.async.cg.shared.global [%0], [%1], 16;"
                 :: "r"(dst), "l"(src) : "memory");
}
static __device__ __forceinline__ void cp_commit() {
    asm volatile("cp.async.commit_group;" ::: "memory");
}
static __device__ __forceinline__ void ldmatrix_x4(uint32_t* r, uint32_t addr) {
    asm volatile("ldmatrix.sync.aligned.m8n8.x4.shared.b16 {%0,%1,%2,%3}, [%4];"
                 : "=r"(r[0]), "=r"(r[1]), "=r"(r[2]), "=r"(r[3]) : "r"(addr));
}
static __device__ __forceinline__ void mma16816(float* c, const uint32_t* a,
                                                uint32_t b0, uint32_t b1) {
    asm volatile("mma.sync.aligned.m16n8k16.row.col.f32.f16.f16.f32 "
                 "{%0,%1,%2,%3}, {%4,%5,%6,%7}, {%8,%9}, {%0,%1,%2,%3};"
                 : "+f"(c[0]), "+f"(c[1]), "+f"(c[2]), "+f"(c[3])
                 : "r"(a[0]), "r"(a[1]), "r"(a[2]), "r"(a[3]), "r"(b0), "r"(b1));
}
static __device__ __forceinline__ uint32_t swz(uint32_t o) {
    return o ^ ((o >> 3) & 0x70);
}
static __device__ __forceinline__ float fast_tanh(float x) {
    float r; asm("tanh.approx.f32 %0, %1;" : "=f"(r) : "f"(x)); return r;
}
static __device__ __forceinline__ float fast_sig(float x) {
    return fmaf(0.5f, fast_tanh(0.5f * x), 0.5f);
}

// SMEM map per CTA (bytes):
//  [0,1024) sBz, [1024,1536) sBs
//  [2048, +8K*2)  A1 stages, [18432, +8K*2) A2 stages
//  [34816, +32K)  Wz (single buffer), [67584, +16K) Ws
#define SM_A1(s)  (2048 + (s) * 8192)
#define SM_A2(s)  (18432 + (s) * 8192)
#define SM_WZ     34816
#define SM_WS     67584
#define SMEM_TOTAL 83968

// ---------------- fused HMMA GEMM + LSTM epilogue ---------------------------
__global__ void __launch_bounds__(256, 2)
lstm_hmma_kernel(const float* __restrict__ c_in,
                 const float* __restrict__ mask,
                 float* __restrict__ out)
{
    extern __shared__ char smem[];
    const int tid  = threadIdx.x;
    const int lane = tid & 31;
    const int wid  = tid >> 5;
    const int warp_m = wid & 1;           // 2 warps x 32 rows
    const int warp_n = wid >> 1;          // 4 warps x 16 j
    const int j0 = blockIdx.x * 64;
    const int m0 = blockIdx.y * 64;

    // stage biases into smem in [g][jl] form
    ((float*)smem)[tid] = g_biasz[(tid >> 6) * 256 + j0 + (tid & 63)];
    if (tid < 128) ((float*)(smem + 1024))[tid] = g_biass[(tid >> 6) * 256 + j0 + (tid & 63)];

    float accz[2][8][4], accs[2][4][4];
    #pragma unroll
    for (int mt = 0; mt < 2; mt++) {
        #pragma unroll
        for (int f = 0; f < 8; f++)
            #pragma unroll
            for (int q = 0; q < 4; q++) accz[mt][f][q] = 0.f;
        #pragma unroll
        for (int f = 0; f < 4; f++)
            #pragma unroll
            for (int q = 0; q < 4; q++) accs[mt][f][q] = 0.f;
    }

    // fragment addressing
    const uint32_t rowA  = warp_m * 32 + (lane & 15);
    const uint32_t axA   = ((lane & 7) * 16) ^ ((lane >> 4) * 16);
    const uint32_t offA  = rowA * 128;
    const uint32_t rowB0 = ((lane >> 4) & 1) * 8 + (lane & 7);
    const uint32_t axB   = ((lane & 7) * 16) ^ (((lane >> 3) & 1) * 16);
    const uint32_t offBz = (warp_n * 64 + rowB0) * 128;
    const uint32_t offBs = (warp_n * 32 + rowB0) * 128;
    const uint32_t sbase = smem_u32(smem);

    auto issue_A = [&](int kb) {
        const uint32_t sg = sbase + SM_A1(kb & 1);
        const bool ph1 = (kb < 4);
        const int c0 = (ph1 ? kb : kb - 4) * 64;
        const __half* a1g = ph1 ? g_Ax : g_Ah;
        #pragma unroll
        for (int i = 0; i < 2; i++) {
            int id = tid + i * 256, r = id >> 3, cc = id & 7;
            cp16(sg + swz(r * 128 + cc * 16),
                 a1g + (size_t)(m0 + r) * 256 + c0 + cc * 8);
        }
        if (!ph1) {
            const uint32_t sg2 = sbase + SM_A2(kb & 1);
            #pragma unroll
            for (int i = 0; i < 2; i++) {
                int id = tid + i * 256, r = id >> 3, cc = id & 7;
                cp16(sg2 + swz(r * 128 + cc * 16),
                     g_As + (size_t)(m0 + r) * 256 + c0 + cc * 8);
            }
        }
        cp_commit();
    };
    auto issue_W = [&](int kb) {
        #pragma unroll
        for (int i = 0; i < 8; i++) {
            int id = tid + i * 256, r = id >> 3, cc = id & 7;
            cp16(sbase + SM_WZ + swz(r * 128 + cc * 16),
                 g_Wz + (size_t)(j0 * 4 + r) * 512 + kb * 64 + cc * 8);
        }
        #pragma unroll
        for (int i = 0; i < 4; i++) {
            int id = tid + i * 256, r = id >> 3, cc = id & 7;
            cp16(sbase + SM_WS + swz(r * 128 + cc * 16),
                 g_Ws + (size_t)(j0 * 2 + r) * 512 + kb * 64 + cc * 8);
        }
        cp_commit();
    };

    issue_A(0);

    #pragma unroll 1
    for (int kb = 0; kb < 8; kb++) {
        issue_W(kb);                 // W buffer free: sync at end of prev chunk
        if (kb < 7) issue_A(kb + 1);
        // FIFO: [.., W(kb), A(kb+1)] -> wait 1 completes A(kb) & W(kb)
        if (kb < 7) asm volatile("cp.async.wait_group 1;" ::: "memory");
        else        asm volatile("cp.async.wait_group 0;" ::: "memory");
        __syncthreads();

        const bool ph2 = (kb >= 4);
        const uint32_t A1b = sbase + SM_A1(kb & 1) + offA;
        const uint32_t A2b = sbase + SM_A2(kb & 1) + offA;
        const uint32_t Wzb = sbase + SM_WZ + offBz;
        const uint32_t Wsb = sbase + SM_WS + offBs;

        #pragma unroll
        for (int kk4 = 0; kk4 < 4; kk4++) {
            const uint32_t KK2 = kk4 * 32;
            uint32_t az[2][4];
            ldmatrix_x4(az[0], A1b + (KK2 ^ axA));
            ldmatrix_x4(az[1], A1b + 16 * 128 + (KK2 ^ axA));
            uint32_t as_[2][4];
            if (ph2) {
                ldmatrix_x4(as_[0], A2b + (KK2 ^ axA));
                ldmatrix_x4(as_[1], A2b + 16 * 128 + (KK2 ^ axA));
            } else {
                #pragma unroll
                for (int q = 0; q < 4; q++) { as_[0][q] = az[0][q]; as_[1][q] = az[1][q]; }
            }
            #pragma unroll
            for (int fp = 0; fp < 2; fp++) {
                uint32_t b[4];
                ldmatrix_x4(b, Wsb + fp * (16 * 128) + (KK2 ^ axB));
                mma16816(accs[0][2 * fp],     as_[0], b[0], b[1]);
                mma16816(accs[1][2 * fp],     as_[1], b[0], b[1]);
                mma16816(accs[0][2 * fp + 1], as_[0], b[2], b[3]);
                mma16816(accs[1][2 * fp + 1], as_[1], b[2], b[3]);
            }
            #pragma unroll
            for (int fp = 0; fp < 4; fp++) {
                uint32_t b[4];
                ldmatrix_x4(b, Wzb + fp * (16 * 128) + (KK2 ^ axB));
                mma16816(accz[0][2 * fp],     az[0], b[0], b[1]);
                mma16816(accz[1][2 * fp],     az[1], b[0], b[1]);
                mma16816(accz[0][2 * fp + 1], az[0], b[2], b[3]);
                mma16816(accz[1][2 * fp + 1], az[1], b[2], b[3]);
            }
        }
        __syncthreads();             // all warps done reading W buffer + A stage
    }

    // ---- register-resident epilogue ----------------------------------------
    const float* sBz = (const float*)smem;
    const float* sBs = (const float*)(smem + 1024);
    const int jb = warp_n * 16 + (lane & 3) * 2;

    #pragma unroll
    for (int mt = 0; mt < 2; mt++) {
        #pragma unroll
        for (int rh = 0; rh < 2; rh++) {
            const int row = m0 + warp_m * 32 + mt * 16 + rh * 8 + (lane >> 2);
            const float mk = mask[row];
            const float* crow = c_in + (size_t)row * H;
            float* orow = out + (size_t)row * H;
            #pragma unroll
            for (int jh = 0; jh < 2; jh++) {
                const int jl = jb + jh * 8;
                const int jg = j0 + jl;
                const float2 cold = *(const float2*)(crow + jg);
                float2 hv, cv, s0v, s1v;
                #pragma unroll
                for (int dj = 0; dj < 2; dj++) {
                    const int q = rh * 2 + dj;
                    float z0 = accz[mt][0 + jh][q] + sBz[0 * 64 + jl + dj];
                    float z1 = accz[mt][2 + jh][q] + sBz[1 * 64 + jl + dj];
                    float z2 = accz[mt][4 + jh][q] + sBz[2 * 64 + jl + dj];
                    float z3 = accz[mt][6 + jh][q] + sBz[3 * 64 + jl + dj];
                    float p0 = accs[mt][0 + jh][q] + sBs[0 * 64 + jl + dj];
                    float p1 = accs[mt][2 + jh][q] + sBs[1 * 64 + jl + dj];

                    float gi = fast_sig(z0);
                    float gf = fast_sig(z1);
                    float go = fast_sig(z2);
                    float ch = fast_tanh(z3);
                    float b0 = fast_sig(p0);
                    float b1 = fast_sig(p1);

                    float cc = (dj == 0) ? cold.x : cold.y;
                    float ct = (gf * cc + gi * ch) * mk;
                    float tc = fast_tanh(ct) * mk;
                    (&hv.x)[dj]  = go * tc;
                    (&cv.x)[dj]  = ct;
                    (&s0v.x)[dj] = b0 * tc;
                    (&s1v.x)[dj] = b1 * tc;
                }
                *(float2*)(orow + jg)                      = hv;
                *(float2*)(orow + (size_t)B_SZ * H + jg)   = cv;
                *(float2*)(orow + 2ull * B_SZ * H + jg)    = s0v;
                *(float2*)(orow + 3ull * B_SZ * H + jg)    = s1v;
            }
        }
    }
}

// ---------------- launch -----------------------------------------------------
extern "C" void kernel_launch(void* const* d_in, const int* in_sizes, int n_in,
                              void* d_out, int out_size) {
    const float* input = (const float*)d_in[0];
    const float* h_m   = (const float*)d_in[1];
    const float* c_m   = (const float*)d_in[2];
    const float* s_m   = (const float*)d_in[3];
    const float* mask  = (const float*)d_in[4];
    const float* w_ih  = (const float*)d_in[5];
    const float* w_hh  = (const float*)d_in[6];
    const float* w_sh  = (const float*)d_in[7];
    const float* b_ih  = (const float*)d_in[8];
    const float* b_hh  = (const float*)d_in[9];
    const float* b_sh  = (const float*)d_in[10];
    const int*   idx   = (const int*)d_in[11];
    float* out = (float*)d_out;

    reorder_kernel<<<768, 1024>>>(w_ih, w_hh, w_sh);
    bias_kernel<<<6, 256>>>(b_ih, b_hh, b_sh);
    aconv_kernel<<<dim3(B_SZ * 256 / 4 / 256, 3), 256>>>(input, h_m, s_m, idx);

    static int smem_set = 0;
    if (!smem_set) {
        cudaFuncSetAttribute(lstm_hmma_kernel,
                             cudaFuncAttributeMaxDynamicSharedMemorySize, SMEM_TOTAL);
        smem_set = 1;
    }
    dim3 grid(4, 1024);
    lstm_hmma_kernel<<<grid, 256, SMEM_TOTAL>>>(c_m, mask, out);
}